// round 2
// baseline (speedup 1.0000x reference)
#include <cuda_runtime.h>
#include <math.h>

// InfoNCE loss, fused GEMM + online logsumexp. f32x2 packed-FMA mainloop.
// Inputs (metadata order): out f32 [512,128], keys f32 [512,512,128], self_index i32 [512]
// Output: scalar f32 loss.

#define BQ      512               // queries
#define DD      128               // embed dim
#define KPB     512               // keys per bag
#define NKEYS   (BQ * KPB)        // 262144 total keys
#define NTILES  (NKEYS / 128)     // 2048 column tiles of 128 keys
#define INV_T   14.285714285714285f
#define NEG_BIG -1.0e30f

typedef unsigned long long u64;

__device__ __forceinline__ u64 pack2(float lo, float hi) {
    u64 r; asm("mov.b64 %0, {%1, %2};" : "=l"(r) : "f"(lo), "f"(hi)); return r;
}
__device__ __forceinline__ void unpack2(u64 v, float& lo, float& hi) {
    asm("mov.b64 {%0, %1}, %2;" : "=f"(lo), "=f"(hi) : "l"(v));
}
// packed dual fp32 FMA (FFMA2) — ptxas never emits this from C++; PTX only.
__device__ __forceinline__ u64 fma2(u64 a, u64 b, u64 c) {
    u64 d; asm("fma.rn.f32x2 %0, %1, %2, %3;" : "=l"(d) : "l"(a), "l"(b), "l"(c)); return d;
}

// Scratch (allocation-free rule: __device__ globals)
__device__ float g_pm[BQ * NTILES];   // per-(row, tile) running max
__device__ float g_ps[BQ * NTILES];   // per-(row, tile) sum exp(l - max)
__device__ float g_posm[BQ * 4];      // own-bag partials (4 tiles per bag)
__device__ float g_poss[BQ * 4];
__device__ float g_loss[BQ];

// ---------------------------------------------------------------------------
// Kernel 1: 128x128 output tile per block (256 threads, 8x8 per thread, the
// 8 columns held as 4 packed f32x2 accumulators). D=128 in four 32-wide
// k-chunks. Epilogue: per-row online (max, sumexp) over the 128-col tile.
// ---------------------------------------------------------------------------
__global__ __launch_bounds__(256, 2)
void gemm_lse(const float* __restrict__ Q, const float* __restrict__ Km,
              const int* __restrict__ sidx)
{
    __shared__ float As[32][132];   // [k][m], padded
    __shared__ float Bs[32][132];   // [k][n]

    const int tid = threadIdx.x;
    const int tx  = tid & 15;       // column group 0..15
    const int ty  = tid >> 4;       // row group 0..15
    const int rowBase = blockIdx.y * 128;   // query rows
    const int colBase = blockIdx.x * 128;   // global key columns

    u64 acc2[8][4];
    #pragma unroll
    for (int i = 0; i < 8; i++)
        #pragma unroll
        for (int j = 0; j < 4; j++) acc2[i][j] = 0ull;   // (+0.0f, +0.0f)

    #pragma unroll 1
    for (int kc = 0; kc < 4; kc++) {
        // Load A (queries) and B (keys) 128x32 chunks, stored transposed [k][mn].
        #pragma unroll
        for (int i = 0; i < 4; i++) {
            int idx = tid + i * 256;        // 0..1023 float4 slots
            int r   = idx >> 3;             // row within tile
            int c   = (idx & 7) * 4;        // k offset within chunk
            float4 va = *(const float4*)(Q  + (rowBase + r) * DD + kc * 32 + c);
            As[c + 0][r] = va.x; As[c + 1][r] = va.y;
            As[c + 2][r] = va.z; As[c + 3][r] = va.w;
            float4 vb = *(const float4*)(Km + (size_t)(colBase + r) * DD + kc * 32 + c);
            Bs[c + 0][r] = vb.x; Bs[c + 1][r] = vb.y;
            Bs[c + 2][r] = vb.z; Bs[c + 3][r] = vb.w;
        }
        __syncthreads();

        #pragma unroll
        for (int kk = 0; kk < 32; kk++) {
            float a[8], b[8];
            #pragma unroll
            for (int i = 0; i < 8; i += 4) {
                float4 t = *(const float4*)&As[kk][ty * 8 + i];
                a[i] = t.x; a[i + 1] = t.y; a[i + 2] = t.z; a[i + 3] = t.w;
            }
            #pragma unroll
            for (int j = 0; j < 8; j += 4) {
                float4 t = *(const float4*)&Bs[kk][tx * 8 + j];
                b[j] = t.x; b[j + 1] = t.y; b[j + 2] = t.z; b[j + 3] = t.w;
            }
            u64 bp[4];
            #pragma unroll
            for (int j = 0; j < 4; j++) bp[j] = pack2(b[2 * j], b[2 * j + 1]);
            #pragma unroll
            for (int i = 0; i < 8; i++) {
                u64 ad = pack2(a[i], a[i]);
                #pragma unroll
                for (int j = 0; j < 4; j++)
                    acc2[i][j] = fma2(ad, bp[j], acc2[i][j]);
            }
        }
        __syncthreads();
    }

    // Epilogue: scale, mask self key, per-row online (max, sumexp) over 128 cols.
    const int bag = colBase >> 9;     // bag owning these 128 keys (128 | 512)
    #pragma unroll
    for (int i = 0; i < 8; i++) {
        const int rg = rowBase + ty * 8 + i;              // global query row
        const int mj = rg * KPB + sidx[rg] - colBase;     // masked col, tile-local

        float l[8];
        #pragma unroll
        for (int j = 0; j < 4; j++) unpack2(acc2[i][j], l[2 * j], l[2 * j + 1]);

        float m = -3.0e38f;
        #pragma unroll
        for (int j = 0; j < 8; j++) {
            int cl = tx * 8 + j;
            float v = l[j] * INV_T;
            if (cl == mj) v = NEG_BIG;                    // self-mask (exp -> 0)
            l[j] = v;
            m = fmaxf(m, v);
        }
        float s = 0.0f;
        #pragma unroll
        for (int j = 0; j < 8; j++) s += __expf(l[j] - m);

        // combine across the 16 lanes sharing this row (fixed order, deterministic)
        #pragma unroll
        for (int off = 8; off > 0; off >>= 1) {
            float mo = __shfl_down_sync(0xFFFFFFFFu, m, off, 16);
            float so = __shfl_down_sync(0xFFFFFFFFu, s, off, 16);
            float M  = fmaxf(m, mo);
            s = s * __expf(m - M) + so * __expf(mo - M);
            m = M;
        }
        if (tx == 0) {
            g_pm[rg * NTILES + blockIdx.x] = m;
            g_ps[rg * NTILES + blockIdx.x] = s;
            if (rg == bag) {                              // own-bag (positive) tile
                int p = blockIdx.x & 3;
                g_posm[rg * 4 + p] = m;
                g_poss[rg * 4 + p] = s;
            }
        }
    }
}

// ---------------------------------------------------------------------------
// Kernel 2: one block per query; reduce 2048 (m,s) partials -> total LSE,
// reduce 4 own-bag partials + 261632 exp(0) terms -> positive LSE, loss_b.
// ---------------------------------------------------------------------------
__global__ void reduce1()
{
    __shared__ float sm[256], ss[256];
    const int b = blockIdx.x, tid = threadIdx.x;

    float m = -3.0e38f, s = 0.0f;
    for (int t = tid; t < NTILES; t += 256) {
        float mo = g_pm[b * NTILES + t], so = g_ps[b * NTILES + t];
        float M  = fmaxf(m, mo);
        s = s * __expf(m - M) + so * __expf(mo - M);
        m = M;
    }
    sm[tid] = m; ss[tid] = s;
    __syncthreads();
    for (int st = 128; st > 0; st >>= 1) {
        if (tid < st) {
            float m1 = sm[tid], m2 = sm[tid + st];
            float s1 = ss[tid], s2 = ss[tid + st];
            float M  = fmaxf(m1, m2);
            sm[tid] = M;
            ss[tid] = s1 * __expf(m1 - M) + s2 * __expf(m2 - M);
        }
        __syncthreads();
    }
    if (tid == 0) {
        float lse_tot = sm[0] + logf(ss[0]);

        float mp = -3.0e38f, sp = 0.0f;
        #pragma unroll
        for (int p = 0; p < 4; p++) {
            float mo = g_posm[b * 4 + p], so = g_poss[b * 4 + p];
            float M  = fmaxf(mp, mo);
            sp = sp * __expf(mp - M) + so * __expf(mo - M);
            mp = M;
        }
        // s_*labels keeps negatives as exp(0)=1: B*K - K = 261632 of them
        float Mp = fmaxf(mp, 0.0f);
        float Sp = sp * __expf(mp - Mp) + 261632.0f * __expf(-Mp);
        float lse_p = Mp + logf(Sp);

        g_loss[b] = -lse_p + logf(511.0f) + lse_tot;     // num_p = 512 -> 511
    }
}

// ---------------------------------------------------------------------------
// Kernel 3: mean over 512 per-query losses.
// ---------------------------------------------------------------------------
__global__ void reduce2(float* __restrict__ out)
{
    __shared__ float sm[512];
    const int tid = threadIdx.x;
    sm[tid] = g_loss[tid];
    __syncthreads();
    for (int st = 256; st > 0; st >>= 1) {
        if (tid < st) sm[tid] += sm[tid + st];
        __syncthreads();
    }
    if (tid == 0) out[0] = sm[0] * (1.0f / 512.0f);
}

// ---------------------------------------------------------------------------
extern "C" void kernel_launch(void* const* d_in, const int* in_sizes, int n_in,
                              void* d_out, int out_size)
{
    const float* Q    = (const float*)d_in[0];   // [512,128]
    const float* Km   = (const float*)d_in[1];   // [512,512,128]
    const int*   sidx = (const int*)  d_in[2];   // [512]

    dim3 grid(NTILES, 4);                        // 2048 col-tiles x 4 row-tiles
    gemm_lse<<<grid, 256>>>(Q, Km, sidx);
    reduce1<<<BQ, 256>>>();
    reduce2<<<1, 512>>>((float*)d_out);
}

// round 4
// speedup vs baseline: 1.6716x; 1.6716x over previous
#include <cuda_runtime.h>
#include <cuda_bf16.h>
#include <math.h>
#include <stdint.h>

// InfoNCE loss: 3-pass bf16-split mma.sync GEMM + fused online LSE.
// (sm_100 plain target: no tcgen05 — HMMA/ldmatrix/cp.async path.)
// Inputs: out f32 [512,128], keys f32 [512,512,128], self_index i32 [512]
// Output: scalar f32 loss.

#define BQ      512
#define DD      128
#define KPB     512
#define NKEYS   (BQ * KPB)
#define TILEN   128
#define NTILES  (NKEYS / TILEN)      // 2048
#define INV_T   14.285714285714285f
#define NEG_BIG -1.0e30f

// ---------------- global scratch (allocation-free rule) ----------------
__device__ __nv_bfloat16 g_ahi[BQ * DD],    g_alo[BQ * DD];     // queries hi/lo
__device__ __nv_bfloat16 g_bhi[NKEYS * DD], g_blo[NKEYS * DD];  // keys hi/lo (64MB each)
__device__ float g_pm[BQ * NTILES], g_ps[BQ * NTILES];
__device__ float g_posm[BQ * 4],    g_poss[BQ * 4];
__device__ float g_loss[BQ];

// ---------------- PTX helpers ----------------
__device__ __forceinline__ uint32_t smem_u32(const void* p) {
    uint32_t a;
    asm("{ .reg .u64 t; cvta.to.shared.u64 t, %1; cvt.u32.u64 %0, t; }" : "=r"(a) : "l"(p));
    return a;
}
__device__ __forceinline__ void ldmx4(uint32_t* r, uint32_t addr) {
    asm volatile("ldmatrix.sync.aligned.m8n8.x4.shared.b16 {%0,%1,%2,%3}, [%4];"
                 : "=r"(r[0]), "=r"(r[1]), "=r"(r[2]), "=r"(r[3]) : "r"(addr));
}
__device__ __forceinline__ void mma16816(float* c, const uint32_t* a, const uint32_t* b) {
    asm volatile("mma.sync.aligned.m16n8k16.row.col.f32.bf16.bf16.f32 "
                 "{%0,%1,%2,%3},{%4,%5,%6,%7},{%8,%9},{%0,%1,%2,%3};"
                 : "+f"(c[0]), "+f"(c[1]), "+f"(c[2]), "+f"(c[3])
                 : "r"(a[0]), "r"(a[1]), "r"(a[2]), "r"(a[3]), "r"(b[0]), "r"(b[1]));
}
#define CPASYNC16(s, g) asm volatile("cp.async.cg.shared.global [%0], [%1], 16;" :: "r"(s), "l"(g))
#define CP_COMMIT()     asm volatile("cp.async.commit_group;" ::: "memory")
#define CP_WAIT0()      asm volatile("cp.async.wait_group 0;" ::: "memory")

// fp32 -> (hi bf16, lo bf16 of residual), 4 at a time
__device__ __forceinline__ void split4(float4 v, uint2& h, uint2& l) {
    float x[4] = {v.x, v.y, v.z, v.w};
    unsigned short hs[4], ls[4];
    #pragma unroll
    for (int i = 0; i < 4; i++) {
        __nv_bfloat16 bh = __float2bfloat16_rn(x[i]);
        float r = x[i] - __bfloat162float(bh);
        __nv_bfloat16 bl = __float2bfloat16_rn(r);
        hs[i] = __bfloat16_as_ushort(bh);
        ls[i] = __bfloat16_as_ushort(bl);
    }
    h.x = (uint32_t)hs[0] | ((uint32_t)hs[1] << 16);
    h.y = (uint32_t)hs[2] | ((uint32_t)hs[3] << 16);
    l.x = (uint32_t)ls[0] | ((uint32_t)ls[1] << 16);
    l.y = (uint32_t)ls[2] | ((uint32_t)ls[3] << 16);
}

// ---------------------------------------------------------------------------
// Kernel 0: split Q and keys into global bf16 hi/lo (same [row][d] layout).
// ---------------------------------------------------------------------------
__global__ __launch_bounds__(256)
void split_kernel(const float* __restrict__ Q, const float* __restrict__ Km)
{
    const int b = blockIdx.x, tid = threadIdx.x;
    if (b < 2048) {                       // keys: 8,388,608 float4 total
        size_t base = (size_t)b * 4096;
        #pragma unroll
        for (int i = 0; i < 16; i++) {
            size_t f = base + tid + i * 256;
            float4 v = ((const float4*)Km)[f];
            uint2 h, l; split4(v, h, l);
            ((uint2*)g_bhi)[f] = h;
            ((uint2*)g_blo)[f] = l;
        }
    } else {                              // queries: 16,384 float4 in 4 blocks
        size_t base = (size_t)(b - 2048) * 4096;
        #pragma unroll
        for (int i = 0; i < 16; i++) {
            size_t f = base + tid + i * 256;
            float4 v = ((const float4*)Q)[f];
            uint2 h, l; split4(v, h, l);
            ((uint2*)g_ahi)[f] = h;
            ((uint2*)g_alo)[f] = l;
        }
    }
}

// ---------------- SMEM layout (dynamic) ----------------
// tiles 128 rows x 128 bf16, padded stride 136 bf16 = 272 B (ldmatrix conflict-free)
#define TSTRIDE 272u
#define TBYTES  34816u                     // 128*272
#define OFF_BHI 0u
#define OFF_BLO 34816u
#define OFF_A0  69632u                     // buf0: HI, LO at +TBYTES
#define OFF_A1  139264u                    // buf1
#define OFF_EM  208896u                    // float [4][128]
#define OFF_ES  210944u
#define SMEM_SZ 212992u

// cp.async one 128x128 bf16 hi+lo tile pair (4096 16B chunks, 16/thread)
__device__ __forceinline__ void load_tile_pair(uint32_t s_hi, uint32_t s_lo,
                                               const __nv_bfloat16* g_hi,
                                               const __nv_bfloat16* g_lo,
                                               int rowBase, int tid)
{
    #pragma unroll
    for (int i = 0; i < 16; i++) {
        int idx  = tid + i * 256;          // 0..4095
        int half = idx >> 11;              // 0 = hi, 1 = lo
        int r    = (idx >> 4) & 127;
        int c    = idx & 15;
        const char* g = (const char*)(half ? g_lo : g_hi)
                      + (size_t)(rowBase + r) * 256 + c * 16;
        uint32_t s = (half ? s_lo : s_hi) + r * TSTRIDE + c * 16;
        CPASYNC16(s, g);
    }
}

// ---------------------------------------------------------------------------
// Kernel 1: one CTA per 128-key tile. B hi/lo resident; loop 4 m-blocks of 128
// queries with double-buffered A. 8 warps, warp tile 64m x 32n. 3 MMA passes
// (hi*hi + hi*lo + lo*hi) into fp32 regs; register-direct LSE epilogue.
// ---------------------------------------------------------------------------
__global__ __launch_bounds__(256, 1)
void gemm_lse_mma(const int* __restrict__ sidx)
{
    extern __shared__ char smem[];
    const uint32_t sb = smem_u32(smem);
    const int tid  = threadIdx.x;
    const int wid  = tid >> 5;
    const int lane = tid & 31;
    const int tile = blockIdx.x;
    const int colBase = tile * TILEN;
    const int wm = (wid & 1) * 64;         // warp m-offset
    const int wn = (wid >> 1) * 32;        // warp n-offset
    const int nw = wid >> 1;               // n-warp index 0..3

    float* smM = (float*)(smem + OFF_EM);
    float* smS = (float*)(smem + OFF_ES);

    // initial loads: B tile (hi+lo) + A(0)
    load_tile_pair(sb + OFF_BHI, sb + OFF_BLO, g_bhi, g_blo, colBase, tid);
    load_tile_pair(sb + OFF_A0, sb + OFF_A0 + TBYTES, g_ahi, g_alo, 0, tid);
    CP_COMMIT();

    #pragma unroll 1
    for (int mb = 0; mb < 4; mb++) {
        CP_WAIT0();
        __syncthreads();
        if (mb < 3) {                      // prefetch next A into other buffer
            uint32_t ab = ((mb + 1) & 1) ? OFF_A1 : OFF_A0;
            load_tile_pair(sb + ab, sb + ab + TBYTES, g_ahi, g_alo, (mb + 1) * 128, tid);
            CP_COMMIT();
        }

        float acc[4][4][4];
        #pragma unroll
        for (int mi = 0; mi < 4; mi++)
            #pragma unroll
            for (int ni = 0; ni < 4; ni++)
                #pragma unroll
                for (int r = 0; r < 4; r++) acc[mi][ni][r] = 0.0f;

        const uint32_t abase = sb + ((mb & 1) ? OFF_A1 : OFF_A0);
        #pragma unroll
        for (int p = 0; p < 3; p++) {
            const uint32_t aoff = abase + (p == 2 ? TBYTES : 0u);
            const uint32_t boff = sb + (p == 1 ? OFF_BLO : OFF_BHI);
            // canonical ldmatrix.x4 lane addressing: (lane&15)=row, (lane>>4)=k-half
            const uint32_t arow = aoff + (wm + (lane & 15)) * TSTRIDE + (lane >> 4) * 16;
            const uint32_t brow = boff + (wn + (lane & 15)) * TSTRIDE + (lane >> 4) * 16;
            #pragma unroll
            for (int kk = 0; kk < 8; kk++) {
                uint32_t a[4][4], bq[8];
                #pragma unroll
                for (int mi = 0; mi < 4; mi++)
                    ldmx4(a[mi], arow + kk * 32 + mi * 16 * TSTRIDE);
                ldmx4(bq,     brow + kk * 32);
                ldmx4(bq + 4, brow + kk * 32 + 16 * TSTRIDE);
                // n8 fragment pairs from the two n16k16 x4-loads
                uint32_t bb[4][2] = {{bq[0], bq[2]}, {bq[1], bq[3]},
                                     {bq[4], bq[6]}, {bq[5], bq[7]}};
                #pragma unroll
                for (int mi = 0; mi < 4; mi++)
                    #pragma unroll
                    for (int ni = 0; ni < 4; ni++)
                        mma16816(acc[mi][ni], a[mi], bb[ni]);
            }
        }

        // ---- epilogue: per-row online (max, sumexp), quad-shuffle reduce ----
        #pragma unroll
        for (int mi = 0; mi < 4; mi++) {
            const int r0l = wm + mi * 16 + (lane >> 2);   // local row (c0,c1)
            const int r1l = r0l + 8;                      // local row (c2,c3)
            const int q0 = mb * 128 + r0l, q1 = mb * 128 + r1l;
            const int msk0 = q0 * KPB + __ldg(&sidx[q0]) - colBase;
            const int msk1 = q1 * KPB + __ldg(&sidx[q1]) - colBase;
            float v0[8], v1[8];
            #pragma unroll
            for (int ni = 0; ni < 4; ni++) {
                const int c = wn + ni * 8 + 2 * (lane & 3);
                float x0 = acc[mi][ni][0] * INV_T; if (c     == msk0) x0 = NEG_BIG;
                float x1 = acc[mi][ni][1] * INV_T; if (c + 1 == msk0) x1 = NEG_BIG;
                float y0 = acc[mi][ni][2] * INV_T; if (c     == msk1) y0 = NEG_BIG;
                float y1 = acc[mi][ni][3] * INV_T; if (c + 1 == msk1) y1 = NEG_BIG;
                v0[2 * ni] = x0; v0[2 * ni + 1] = x1;
                v1[2 * ni] = y0; v1[2 * ni + 1] = y1;
            }
            float m0 = -3.0e38f, m1 = -3.0e38f;
            #pragma unroll
            for (int j = 0; j < 8; j++) { m0 = fmaxf(m0, v0[j]); m1 = fmaxf(m1, v1[j]); }
            float s0 = 0.0f, s1 = 0.0f;
            #pragma unroll
            for (int j = 0; j < 8; j++) {
                s0 += __expf(v0[j] - m0);
                s1 += __expf(v1[j] - m1);
            }
            #pragma unroll
            for (int o = 1; o < 4; o <<= 1) {             // reduce over lane quad
                float mo = __shfl_xor_sync(0xFFFFFFFFu, m0, o);
                float so = __shfl_xor_sync(0xFFFFFFFFu, s0, o);
                float M  = fmaxf(m0, mo);
                s0 = s0 * __expf(m0 - M) + so * __expf(mo - M); m0 = M;
                mo = __shfl_xor_sync(0xFFFFFFFFu, m1, o);
                so = __shfl_xor_sync(0xFFFFFFFFu, s1, o);
                M  = fmaxf(m1, mo);
                s1 = s1 * __expf(m1 - M) + so * __expf(mo - M); m1 = M;
            }
            if ((lane & 3) == 0) {
                smM[nw * 128 + r0l] = m0; smS[nw * 128 + r0l] = s0;
                smM[nw * 128 + r1l] = m1; smS[nw * 128 + r1l] = s1;
            }
        }
        __syncthreads();
        if (tid < 128) {                   // combine 4 n-warp partials per row
            float m = -3.0e38f, s = 0.0f;
            #pragma unroll
            for (int w = 0; w < 4; w++) {
                float mo = smM[w * 128 + tid], so = smS[w * 128 + tid];
                float M = fmaxf(m, mo);
                s = s * __expf(m - M) + so * __expf(mo - M);
                m = M;
            }
            const int q = mb * 128 + tid;
            g_pm[q * NTILES + tile] = m;
            g_ps[q * NTILES + tile] = s;
            if (q == (tile >> 2)) {        // positive (own-bag) tile
                g_posm[q * 4 + (tile & 3)] = m;
                g_poss[q * 4 + (tile & 3)] = s;
            }
        }
    }
}

// ---------------------------------------------------------------------------
// Kernel 2: per query, reduce 2048 (m,s) partials -> total LSE; own-bag
// partials + 261632 exp(0) terms -> positive LSE; per-query loss.
// ---------------------------------------------------------------------------
__global__ void reduce1()
{
    __shared__ float sm[256], ss[256];
    const int b = blockIdx.x, tid = threadIdx.x;

    float m = -3.0e38f, s = 0.0f;
    for (int t = tid; t < NTILES; t += 256) {
        float mo = g_pm[b * NTILES + t], so = g_ps[b * NTILES + t];
        float M = fmaxf(m, mo);
        s = s * __expf(m - M) + so * __expf(mo - M);
        m = M;
    }
    sm[tid] = m; ss[tid] = s;
    __syncthreads();
    for (int st = 128; st > 0; st >>= 1) {
        if (tid < st) {
            float m1 = sm[tid], m2 = sm[tid + st];
            float s1 = ss[tid], s2 = ss[tid + st];
            float M = fmaxf(m1, m2);
            sm[tid] = M;
            ss[tid] = s1 * __expf(m1 - M) + s2 * __expf(m2 - M);
        }
        __syncthreads();
    }
    if (tid == 0) {
        float lse_tot = sm[0] + logf(ss[0]);

        float mp = -3.0e38f, sp = 0.0f;
        #pragma unroll
        for (int p = 0; p < 4; p++) {
            float mo = g_posm[b * 4 + p], so = g_poss[b * 4 + p];
            float M = fmaxf(mp, mo);
            sp = sp * __expf(mp - M) + so * __expf(mo - M);
            mp = M;
        }
        // s_*labels keeps negatives as exp(0)=1: B*K - K = 261632 of them
        float Mp = fmaxf(mp, 0.0f);
        float Sp = sp * __expf(mp - Mp) + 261632.0f * __expf(-Mp);
        float lse_p = Mp + logf(Sp);

        g_loss[b] = -lse_p + logf(511.0f) + lse_tot;      // num_p = 512 -> 511
    }
}

__global__ void reduce2(float* __restrict__ out)
{
    __shared__ float sm[512];
    const int tid = threadIdx.x;
    sm[tid] = g_loss[tid];
    __syncthreads();
    for (int st = 256; st > 0; st >>= 1) {
        if (tid < st) sm[tid] += sm[tid + st];
        __syncthreads();
    }
    if (tid == 0) out[0] = sm[0] * (1.0f / 512.0f);
}

// ---------------------------------------------------------------------------
extern "C" void kernel_launch(void* const* d_in, const int* in_sizes, int n_in,
                              void* d_out, int out_size)
{
    const float* Q    = (const float*)d_in[0];   // [512,128]
    const float* Km   = (const float*)d_in[1];   // [512,512,128]
    const int*   sidx = (const int*)  d_in[2];   // [512]

    cudaFuncSetAttribute(gemm_lse_mma, cudaFuncAttributeMaxDynamicSharedMemorySize, SMEM_SZ);

    split_kernel<<<2052, 256>>>(Q, Km);
    gemm_lse_mma<<<NTILES, 256, SMEM_SZ>>>(sidx);
    reduce1<<<BQ, 256>>>();
    reduce2<<<1, 512>>>((float*)d_out);
}

// round 5
// speedup vs baseline: 2.7999x; 1.6749x over previous
#include <cuda_runtime.h>
#include <math.h>
#include <stdint.h>

// InfoNCE loss: 3-pass int8-split IMMA GEMM + fused online LSE.
// dot*S^2 = 16384*(h.h) + 128*(h.l + l.h)   [l.l dropped; zero-mean, averages out]
// Inputs: out f32 [512,128], keys f32 [512,512,128], self_index i32 [512]
// Output: scalar f32 loss.

#define BQ      512
#define DD      128
#define KPB     512
#define NKEYS   (BQ * KPB)
#define TILEN   128
#define NTILES  (NKEYS / TILEN)      // 2048
#define INV_T   14.285714285714285f
#define NEG_BIG -1.0e30f
// S = 2048; C1 = 16384*INV_T/S^2, C2 = 128*INV_T/S^2
#define QC1     0.05580357142857143f
#define QC2     4.359654017857143e-4f

// ---------------- global scratch (allocation-free rule) ----------------
__device__ int8_t g_ah[BQ * DD],    g_al[BQ * DD];      // queries hi/lo int8
__device__ int8_t g_bh[NKEYS * DD], g_bl[NKEYS * DD];   // keys hi/lo int8 (32MB each)
__device__ float g_pm[BQ * NTILES], g_ps[BQ * NTILES];
__device__ float g_posm[BQ * 4],    g_poss[BQ * 4];
__device__ float g_loss[BQ];

// ---------------- PTX helpers ----------------
__device__ __forceinline__ uint32_t smem_u32(const void* p) {
    uint32_t a;
    asm("{ .reg .u64 t; cvta.to.shared.u64 t, %1; cvt.u32.u64 %0, t; }" : "=r"(a) : "l"(p));
    return a;
}
__device__ __forceinline__ void ldmx4(uint32_t* r, uint32_t addr) {
    asm volatile("ldmatrix.sync.aligned.m8n8.x4.shared.b16 {%0,%1,%2,%3}, [%4];"
                 : "=r"(r[0]), "=r"(r[1]), "=r"(r[2]), "=r"(r[3]) : "r"(addr));
}
__device__ __forceinline__ void imma16832(int* c, const uint32_t* a, const uint32_t* b) {
    asm volatile("mma.sync.aligned.m16n8k32.row.col.s32.s8.s8.s32 "
                 "{%0,%1,%2,%3},{%4,%5,%6,%7},{%8,%9},{%0,%1,%2,%3};"
                 : "+r"(c[0]), "+r"(c[1]), "+r"(c[2]), "+r"(c[3])
                 : "r"(a[0]), "r"(a[1]), "r"(a[2]), "r"(a[3]), "r"(b[0]), "r"(b[1]));
}
#define CPASYNC16(s, g) asm volatile("cp.async.cg.shared.global [%0], [%1], 16;" :: "r"(s), "l"(g))
#define CP_COMMIT()     asm volatile("cp.async.commit_group;" ::: "memory")
#define CP_WAIT0()      asm volatile("cp.async.wait_group 0;" ::: "memory")

// fp32 -> (h, l) int8 pair: xi = rint(2048 x) clamped, xi = 128 h + l, l in [-64,63]
__device__ __forceinline__ void quant4(float4 v, uint32_t& hp, uint32_t& lp) {
    float x[4] = {v.x, v.y, v.z, v.w};
    uint32_t h = 0, l = 0;
    #pragma unroll
    for (int i = 0; i < 4; i++) {
        int xi = __float2int_rn(x[i] * 2048.0f);
        xi = max(-16256, min(16255, xi));
        int hi = (xi + 64) >> 7;           // [-127,127]
        int lo = xi - (hi << 7);           // [-64,63]
        h |= (uint32_t)(hi & 0xFF) << (8 * i);
        l |= (uint32_t)(lo & 0xFF) << (8 * i);
    }
    hp = h; lp = l;
}

// ---------------------------------------------------------------------------
// Kernel 0: quantize Q and keys into global int8 h/l (same [row][d] layout).
// ---------------------------------------------------------------------------
__global__ __launch_bounds__(256)
void quant_kernel(const float* __restrict__ Q, const float* __restrict__ Km)
{
    const int b = blockIdx.x, tid = threadIdx.x;
    if (b < 2048) {                        // keys: 8,388,608 float4 total
        size_t base = (size_t)b * 4096;
        #pragma unroll
        for (int i = 0; i < 16; i++) {
            size_t f = base + tid + i * 256;
            float4 v = ((const float4*)Km)[f];
            uint32_t h, l; quant4(v, h, l);
            ((uint32_t*)g_bh)[f] = h;
            ((uint32_t*)g_bl)[f] = l;
        }
    } else {                               // queries: 16,384 float4 in 4 blocks
        size_t base = (size_t)(b - 2048) * 4096;
        #pragma unroll
        for (int i = 0; i < 16; i++) {
            size_t f = base + tid + i * 256;
            float4 v = ((const float4*)Q)[f];
            uint32_t h, l; quant4(v, h, l);
            ((uint32_t*)g_ah)[f] = h;
            ((uint32_t*)g_al)[f] = l;
        }
    }
}

// ---------------- SMEM layout ----------------
// tiles 128 rows x 128 int8, padded stride 144 B (ldmatrix conflict-free)
#define TSTRIDE 144u
#define TBYTES  18432u                     // 128*144
#define OFF_BH  0u
#define OFF_BL  18432u
#define OFF_A0  36864u                     // buf: H, L at +TBYTES
#define OFF_A1  73728u
#define OFF_EM  110592u                    // float [4][128]
#define OFF_ES  112640u
#define SMEM_SZ 114688u

// cp.async one 128x128 int8 h+l tile pair (2048 16B chunks, 8/thread)
__device__ __forceinline__ void load_tile_pair(uint32_t s_h, uint32_t s_l,
                                               const int8_t* g_h, const int8_t* g_l,
                                               int rowBase, int tid)
{
    #pragma unroll
    for (int i = 0; i < 8; i++) {
        int idx  = tid + i * 256;          // 0..2047
        int half = idx >> 10;              // 0 = h, 1 = l
        int r    = (idx >> 3) & 127;
        int c    = idx & 7;
        const char* g = (const char*)(half ? g_l : g_h)
                      + (size_t)(rowBase + r) * 128 + c * 16;
        uint32_t s = (half ? s_l : s_h) + r * TSTRIDE + c * 16;
        CPASYNC16(s, g);
    }
}

// ---------------------------------------------------------------------------
// Kernel 1: one CTA per 128-key tile. B h/l resident; loop 4 m-blocks of 128
// queries with double-buffered A. 8 warps, warp tile 64m x 32n. Pass 1 (h.h)
// into accH, passes 2+3 (h.l + l.h, shared scale 128) into accC.
// ---------------------------------------------------------------------------
__global__ __launch_bounds__(256, 1)
void gemm_lse_imma(const int* __restrict__ sidx)
{
    extern __shared__ char smem[];
    const uint32_t sb = smem_u32(smem);
    const int tid  = threadIdx.x;
    const int wid  = tid >> 5;
    const int lane = tid & 31;
    const int tile = blockIdx.x;
    const int colBase = tile * TILEN;
    const int wm = (wid & 1) * 64;
    const int wn = (wid >> 1) * 32;
    const int nw = wid >> 1;

    float* smM = (float*)(smem + OFF_EM);
    float* smS = (float*)(smem + OFF_ES);

    load_tile_pair(sb + OFF_BH, sb + OFF_BL, g_bh, g_bl, colBase, tid);
    load_tile_pair(sb + OFF_A0, sb + OFF_A0 + TBYTES, g_ah, g_al, 0, tid);
    CP_COMMIT();

    #pragma unroll 1
    for (int mb = 0; mb < 4; mb++) {
        CP_WAIT0();
        __syncthreads();
        if (mb < 3) {
            uint32_t ab = ((mb + 1) & 1) ? OFF_A1 : OFF_A0;
            load_tile_pair(sb + ab, sb + ab + TBYTES, g_ah, g_al, (mb + 1) * 128, tid);
            CP_COMMIT();
        }

        int accH[4][4][4], accC[4][4][4];
        #pragma unroll
        for (int mi = 0; mi < 4; mi++)
            #pragma unroll
            for (int ni = 0; ni < 4; ni++)
                #pragma unroll
                for (int r = 0; r < 4; r++) { accH[mi][ni][r] = 0; accC[mi][ni][r] = 0; }

        const uint32_t abase = sb + ((mb & 1) ? OFF_A1 : OFF_A0);
        #pragma unroll
        for (int p = 0; p < 3; p++) {
            // p0: ah.bh -> accH | p1: ah.bl -> accC | p2: al.bh -> accC
            const uint32_t aoff = abase + (p == 2 ? TBYTES : 0u);
            const uint32_t boff = sb + (p == 1 ? OFF_BL : OFF_BH);
            const uint32_t arow = aoff + (wm + (lane & 15)) * TSTRIDE + (lane >> 4) * 16;
            const uint32_t brow = boff + (wn + (lane & 15)) * TSTRIDE + (lane >> 4) * 16;
            #pragma unroll
            for (int kk = 0; kk < 4; kk++) {            // 4 k-steps of 32 bytes
                uint32_t a[4][4], bq[8];
                #pragma unroll
                for (int mi = 0; mi < 4; mi++)
                    ldmx4(a[mi], arow + kk * 32 + mi * 16 * TSTRIDE);
                ldmx4(bq,     brow + kk * 32);
                ldmx4(bq + 4, brow + kk * 32 + 16 * TSTRIDE);
                uint32_t bb[4][2] = {{bq[0], bq[2]}, {bq[1], bq[3]},
                                     {bq[4], bq[6]}, {bq[5], bq[7]}};
                int (*acc)[4][4] = (p == 0) ? accH : accC;
                #pragma unroll
                for (int mi = 0; mi < 4; mi++)
                    #pragma unroll
                    for (int ni = 0; ni < 4; ni++)
                        imma16832(acc[mi][ni], a[mi], bb[ni]);
            }
        }

        // ---- epilogue: per-row online (max, sumexp), quad-shuffle reduce ----
        #pragma unroll
        for (int mi = 0; mi < 4; mi++) {
            const int r0l = wm + mi * 16 + (lane >> 2);
            const int r1l = r0l + 8;
            const int q0 = mb * 128 + r0l, q1 = mb * 128 + r1l;
            const int msk0 = q0 * KPB + __ldg(&sidx[q0]) - colBase;
            const int msk1 = q1 * KPB + __ldg(&sidx[q1]) - colBase;
            float v0[8], v1[8];
            #pragma unroll
            for (int ni = 0; ni < 4; ni++) {
                const int c = wn + ni * 8 + 2 * (lane & 3);
                float x0 = fmaf((float)accH[mi][ni][0], QC1, (float)accC[mi][ni][0] * QC2);
                float x1 = fmaf((float)accH[mi][ni][1], QC1, (float)accC[mi][ni][1] * QC2);
                float y0 = fmaf((float)accH[mi][ni][2], QC1, (float)accC[mi][ni][2] * QC2);
                float y1 = fmaf((float)accH[mi][ni][3], QC1, (float)accC[mi][ni][3] * QC2);
                if (c     == msk0) x0 = NEG_BIG;
                if (c + 1 == msk0) x1 = NEG_BIG;
                if (c     == msk1) y0 = NEG_BIG;
                if (c + 1 == msk1) y1 = NEG_BIG;
                v0[2 * ni] = x0; v0[2 * ni + 1] = x1;
                v1[2 * ni] = y0; v1[2 * ni + 1] = y1;
            }
            float m0 = -3.0e38f, m1 = -3.0e38f;
            #pragma unroll
            for (int j = 0; j < 8; j++) { m0 = fmaxf(m0, v0[j]); m1 = fmaxf(m1, v1[j]); }
            float s0 = 0.0f, s1 = 0.0f;
            #pragma unroll
            for (int j = 0; j < 8; j++) {
                s0 += __expf(v0[j] - m0);
                s1 += __expf(v1[j] - m1);
            }
            #pragma unroll
            for (int o = 1; o < 4; o <<= 1) {
                float mo = __shfl_xor_sync(0xFFFFFFFFu, m0, o);
                float so = __shfl_xor_sync(0xFFFFFFFFu, s0, o);
                float M  = fmaxf(m0, mo);
                s0 = s0 * __expf(m0 - M) + so * __expf(mo - M); m0 = M;
                mo = __shfl_xor_sync(0xFFFFFFFFu, m1, o);
                so = __shfl_xor_sync(0xFFFFFFFFu, s1, o);
                M  = fmaxf(m1, mo);
                s1 = s1 * __expf(m1 - M) + so * __expf(mo - M); m1 = M;
            }
            if ((lane & 3) == 0) {
                smM[nw * 128 + r0l] = m0; smS[nw * 128 + r0l] = s0;
                smM[nw * 128 + r1l] = m1; smS[nw * 128 + r1l] = s1;
            }
        }
        __syncthreads();
        if (tid < 128) {
            float m = -3.0e38f, s = 0.0f;
            #pragma unroll
            for (int w = 0; w < 4; w++) {
                float mo = smM[w * 128 + tid], so = smS[w * 128 + tid];
                float M = fmaxf(m, mo);
                s = s * __expf(m - M) + so * __expf(mo - M);
                m = M;
            }
            const int q = mb * 128 + tid;
            g_pm[q * NTILES + tile] = m;
            g_ps[q * NTILES + tile] = s;
            if (q == (tile >> 2)) {
                g_posm[q * 4 + (tile & 3)] = m;
                g_poss[q * 4 + (tile & 3)] = s;
            }
        }
    }
}

// ---------------------------------------------------------------------------
// Kernel 2: per query, reduce 2048 (m,s) partials -> total LSE; own-bag
// partials + 261632 exp(0) terms -> positive LSE; per-query loss.
// ---------------------------------------------------------------------------
__global__ void reduce1()
{
    __shared__ float sm[256], ss[256];
    const int b = blockIdx.x, tid = threadIdx.x;

    float m = -3.0e38f, s = 0.0f;
    for (int t = tid; t < NTILES; t += 256) {
        float mo = g_pm[b * NTILES + t], so = g_ps[b * NTILES + t];
        float M = fmaxf(m, mo);
        s = s * __expf(m - M) + so * __expf(mo - M);
        m = M;
    }
    sm[tid] = m; ss[tid] = s;
    __syncthreads();
    for (int st = 128; st > 0; st >>= 1) {
        if (tid < st) {
            float m1 = sm[tid], m2 = sm[tid + st];
            float s1 = ss[tid], s2 = ss[tid + st];
            float M = fmaxf(m1, m2);
            sm[tid] = M;
            ss[tid] = s1 * __expf(m1 - M) + s2 * __expf(m2 - M);
        }
        __syncthreads();
    }
    if (tid == 0) {
        float lse_tot = sm[0] + logf(ss[0]);

        float mp = -3.0e38f, sp = 0.0f;
        #pragma unroll
        for (int p = 0; p < 4; p++) {
            float mo = g_posm[b * 4 + p], so = g_poss[b * 4 + p];
            float M = fmaxf(mp, mo);
            sp = sp * __expf(mp - M) + so * __expf(mo - M);
            mp = M;
        }
        // s_*labels keeps negatives as exp(0)=1: B*K - K = 261632 of them
        float Mp = fmaxf(mp, 0.0f);
        float Sp = sp * __expf(mp - Mp) + 261632.0f * __expf(-Mp);
        float lse_p = Mp + logf(Sp);

        g_loss[b] = -lse_p + logf(511.0f) + lse_tot;      // num_p = 512 -> 511
    }
}

__global__ void reduce2(float* __restrict__ out)
{
    __shared__ float sm[512];
    const int tid = threadIdx.x;
    sm[tid] = g_loss[tid];
    __syncthreads();
    for (int st = 256; st > 0; st >>= 1) {
        if (tid < st) sm[tid] += sm[tid + st];
        __syncthreads();
    }
    if (tid == 0) out[0] = sm[0] * (1.0f / 512.0f);
}

// ---------------------------------------------------------------------------
extern "C" void kernel_launch(void* const* d_in, const int* in_sizes, int n_in,
                              void* d_out, int out_size)
{
    const float* Q    = (const float*)d_in[0];   // [512,128]
    const float* Km   = (const float*)d_in[1];   // [512,512,128]
    const int*   sidx = (const int*)  d_in[2];   // [512]

    cudaFuncSetAttribute(gemm_lse_imma, cudaFuncAttributeMaxDynamicSharedMemorySize, SMEM_SZ);

    quant_kernel<<<2052, 256>>>(Q, Km);
    gemm_lse_imma<<<NTILES, 256, SMEM_SZ>>>(sidx);
    reduce1<<<BQ, 256>>>();
    reduce2<<<1, 512>>>((float*)d_out);
}

// round 6
// speedup vs baseline: 4.6795x; 1.6713x over previous
#include <cuda_runtime.h>
#include <cuda_fp16.h>
#include <math.h>
#include <stdint.h>

// InfoNCE loss: single-pass fp16 HMMA GEMM (f32 acc) + fused online LSE.
// fp16 inputs give 11-bit mantissa -> logit rms err ~0.06, far under tolerance.
// Inputs: out f32 [512,128], keys f32 [512,512,128], self_index i32 [512]
// Output: scalar f32 loss.

#define BQ      512
#define DD      128
#define KPB     512
#define NKEYS   (BQ * KPB)
#define TILEN   128
#define NTILES  (NKEYS / TILEN)      // 2048
#define INV_T   14.285714285714285f
#define NEG_BIG -1.0e30f

// ---------------- global scratch (allocation-free rule) ----------------
__device__ __align__(256) __half g_qh[BQ * DD];          // queries fp16
__device__ float g_pm[BQ * NTILES], g_ps[BQ * NTILES];
__device__ float g_posm[BQ * 4],    g_poss[BQ * 4];
__device__ float g_loss[BQ];

// ---------------- PTX helpers ----------------
__device__ __forceinline__ uint32_t smem_u32(const void* p) {
    uint32_t a;
    asm("{ .reg .u64 t; cvta.to.shared.u64 t, %1; cvt.u32.u64 %0, t; }" : "=r"(a) : "l"(p));
    return a;
}
__device__ __forceinline__ void ldmx4(uint32_t* r, uint32_t addr) {
    asm volatile("ldmatrix.sync.aligned.m8n8.x4.shared.b16 {%0,%1,%2,%3}, [%4];"
                 : "=r"(r[0]), "=r"(r[1]), "=r"(r[2]), "=r"(r[3]) : "r"(addr));
}
__device__ __forceinline__ void hmma16816(float* c, const uint32_t* a, const uint32_t* b) {
    asm volatile("mma.sync.aligned.m16n8k16.row.col.f32.f16.f16.f32 "
                 "{%0,%1,%2,%3},{%4,%5,%6,%7},{%8,%9},{%0,%1,%2,%3};"
                 : "+f"(c[0]), "+f"(c[1]), "+f"(c[2]), "+f"(c[3])
                 : "r"(a[0]), "r"(a[1]), "r"(a[2]), "r"(a[3]), "r"(b[0]), "r"(b[1]));
}
#define CPASYNC16(s, g) asm volatile("cp.async.cg.shared.global [%0], [%1], 16;" :: "r"(s), "l"(g))
#define CP_COMMIT()     asm volatile("cp.async.commit_group;" ::: "memory")
#define CP_WAIT0()      asm volatile("cp.async.wait_group 0;" ::: "memory")

// ---------------------------------------------------------------------------
// Kernel 0: convert queries f32 -> fp16 (tiny: 256 KB read).
// ---------------------------------------------------------------------------
__global__ __launch_bounds__(256)
void qconv(const float* __restrict__ Q)
{
    const int t = blockIdx.x * 256 + threadIdx.x;      // 4096 threads
    #pragma unroll
    for (int i = 0; i < 4; i++) {
        int f = t + i * 4096;                          // float4 index 0..16383
        float4 v = ((const float4*)Q)[f];
        __half2 h0 = __floats2half2_rn(v.x, v.y);
        __half2 h1 = __floats2half2_rn(v.z, v.w);
        ((uint2*)g_qh)[f] = make_uint2(*(uint32_t*)&h0, *(uint32_t*)&h1);
    }
}

// ---------------- SMEM layout ----------------
// tiles 128 rows x 128 fp16, padded stride 272 B (17 x 16B -> ldmatrix conflict-free)
#define TSTRIDE 272u
#define TBYTES  34816u
#define OFF_B   0u
#define OFF_A   34816u
#define OFF_EM  69632u                      // float [4][128]
#define OFF_ES  71680u
#define SMEM_SZ 73728u

// cp.async one 128x128 fp16 tile from global fp16 (2048 16B chunks, 8/thread)
__device__ __forceinline__ void load_a_tile(uint32_t s_a, const __half* g, int rowBase, int tid)
{
    #pragma unroll
    for (int i = 0; i < 8; i++) {
        int idx = tid + i * 256;            // 0..2047
        int r   = idx >> 4;
        int c   = idx & 15;
        const char* gp = (const char*)g + (size_t)(rowBase + r) * 256 + c * 16;
        CPASYNC16(s_a + r * TSTRIDE + c * 16, gp);
    }
}

// ---------------------------------------------------------------------------
// Kernel 1: one CTA per 128-key tile; B converted f32->f16 in-CTA (keys read
// once from DRAM); loop 4 m-blocks of 128 queries, A prefetched into the same
// buffer during the epilogue. 8 warps, warp tile 64m x 32n, single f16 pass.
// ---------------------------------------------------------------------------
__global__ __launch_bounds__(256, 2)
void gemm_lse_hmma(const float* __restrict__ Km, const int* __restrict__ sidx)
{
    extern __shared__ char smem[];
    const uint32_t sb = smem_u32(smem);
    const int tid  = threadIdx.x;
    const int wid  = tid >> 5;
    const int lane = tid & 31;
    const int tile = blockIdx.x;
    const int colBase = tile * TILEN;
    const int wm = (wid & 1) * 64;
    const int wn = (wid >> 1) * 32;
    const int nw = wid >> 1;

    float* smM = (float*)(smem + OFF_EM);
    float* smS = (float*)(smem + OFF_ES);

    // kick A(0) prefetch, then convert B tile f32 -> f16 smem (hides LDG latency)
    load_a_tile(sb + OFF_A, g_qh, 0, tid);
    CP_COMMIT();
    #pragma unroll
    for (int i = 0; i < 16; i++) {
        int f  = tid + i * 256;             // float4 index 0..4095 (32 per row)
        int r  = f >> 5;
        int c4 = f & 31;
        float4 v = *(const float4*)(Km + (size_t)(colBase + r) * DD + c4 * 4);
        __half2 h0 = __floats2half2_rn(v.x, v.y);
        __half2 h1 = __floats2half2_rn(v.z, v.w);
        *(uint2*)(smem + OFF_B + r * TSTRIDE + c4 * 8)
            = make_uint2(*(uint32_t*)&h0, *(uint32_t*)&h1);
    }
    CP_WAIT0();
    __syncthreads();

    #pragma unroll 1
    for (int mb = 0; mb < 4; mb++) {
        float acc[4][4][4];
        #pragma unroll
        for (int mi = 0; mi < 4; mi++)
            #pragma unroll
            for (int ni = 0; ni < 4; ni++)
                #pragma unroll
                for (int r = 0; r < 4; r++) acc[mi][ni][r] = 0.0f;

        const uint32_t arow = sb + OFF_A + (wm + (lane & 15)) * TSTRIDE + (lane >> 4) * 16;
        const uint32_t brow = sb + OFF_B + (wn + (lane & 15)) * TSTRIDE + (lane >> 4) * 16;
        #pragma unroll
        for (int kk = 0; kk < 8; kk++) {                // 8 k-steps of 16 halves
            uint32_t a[4][4], bq[8];
            #pragma unroll
            for (int mi = 0; mi < 4; mi++)
                ldmx4(a[mi], arow + kk * 32 + mi * 16 * TSTRIDE);
            ldmx4(bq,     brow + kk * 32);
            ldmx4(bq + 4, brow + kk * 32 + 16 * TSTRIDE);
            uint32_t bb[4][2] = {{bq[0], bq[2]}, {bq[1], bq[3]},
                                 {bq[4], bq[6]}, {bq[5], bq[7]}};
            #pragma unroll
            for (int mi = 0; mi < 4; mi++)
                #pragma unroll
                for (int ni = 0; ni < 4; ni++)
                    hmma16816(acc[mi][ni], a[mi], bb[ni]);
        }

        __syncthreads();                    // all warps done reading A smem
        if (mb < 3) {                       // prefetch next A under the epilogue
            load_a_tile(sb + OFF_A, g_qh, (mb + 1) * 128, tid);
            CP_COMMIT();
        }

        // ---- epilogue: max-first per-row (max, sumexp), quad-shuffle reduce ----
        #pragma unroll
        for (int mi = 0; mi < 4; mi++) {
            const int r0l = wm + mi * 16 + (lane >> 2);
            const int r1l = r0l + 8;
            const int q0 = mb * 128 + r0l, q1 = mb * 128 + r1l;
            const int msk0 = q0 * KPB + __ldg(&sidx[q0]) - colBase;
            const int msk1 = q1 * KPB + __ldg(&sidx[q1]) - colBase;
            float v0[8], v1[8];
            #pragma unroll
            for (int ni = 0; ni < 4; ni++) {
                const int c = wn + ni * 8 + 2 * (lane & 3);
                float x0 = acc[mi][ni][0] * INV_T; if (c     == msk0) x0 = NEG_BIG;
                float x1 = acc[mi][ni][1] * INV_T; if (c + 1 == msk0) x1 = NEG_BIG;
                float y0 = acc[mi][ni][2] * INV_T; if (c     == msk1) y0 = NEG_BIG;
                float y1 = acc[mi][ni][3] * INV_T; if (c + 1 == msk1) y1 = NEG_BIG;
                v0[2 * ni] = x0; v0[2 * ni + 1] = x1;
                v1[2 * ni] = y0; v1[2 * ni + 1] = y1;
            }
            float m0 = -3.0e38f, m1 = -3.0e38f;
            #pragma unroll
            for (int j = 0; j < 8; j++) { m0 = fmaxf(m0, v0[j]); m1 = fmaxf(m1, v1[j]); }
            #pragma unroll
            for (int o = 1; o < 4; o <<= 1) {           // row max over the quad
                m0 = fmaxf(m0, __shfl_xor_sync(0xFFFFFFFFu, m0, o));
                m1 = fmaxf(m1, __shfl_xor_sync(0xFFFFFFFFu, m1, o));
            }
            float s0 = 0.0f, s1 = 0.0f;
            #pragma unroll
            for (int j = 0; j < 8; j++) {
                s0 += __expf(v0[j] - m0);
                s1 += __expf(v1[j] - m1);
            }
            #pragma unroll
            for (int o = 1; o < 4; o <<= 1) {           // row sum over the quad
                s0 += __shfl_xor_sync(0xFFFFFFFFu, s0, o);
                s1 += __shfl_xor_sync(0xFFFFFFFFu, s1, o);
            }
            if ((lane & 3) == 0) {
                smM[nw * 128 + r0l] = m0; smS[nw * 128 + r0l] = s0;
                smM[nw * 128 + r1l] = m1; smS[nw * 128 + r1l] = s1;
            }
        }
        __syncthreads();
        if (tid < 128) {                    // combine 4 n-warp partials per row
            float m = -3.0e38f, s = 0.0f;
            #pragma unroll
            for (int w = 0; w < 4; w++) {
                float mo = smM[w * 128 + tid], so = smS[w * 128 + tid];
                float M = fmaxf(m, mo);
                s = s * __expf(m - M) + so * __expf(mo - M);
                m = M;
            }
            const int q = mb * 128 + tid;
            g_pm[q * NTILES + tile] = m;
            g_ps[q * NTILES + tile] = s;
            if (q == (tile >> 2)) {         // positive (own-bag) tile
                g_posm[q * 4 + (tile & 3)] = m;
                g_poss[q * 4 + (tile & 3)] = s;
            }
        }
        CP_WAIT0();
        __syncthreads();                    // next A tile resident
    }
}

// ---------------------------------------------------------------------------
// Kernel 2: per query, reduce 2048 (m,s) partials -> total LSE; own-bag
// partials + 261632 exp(0) terms -> positive LSE; per-query loss.
// ---------------------------------------------------------------------------
__global__ void reduce1()
{
    __shared__ float sm[256], ss[256];
    const int b = blockIdx.x, tid = threadIdx.x;

    float m = -3.0e38f, s = 0.0f;
    for (int t = tid; t < NTILES; t += 256) {
        float mo = g_pm[b * NTILES + t], so = g_ps[b * NTILES + t];
        float M = fmaxf(m, mo);
        s = s * __expf(m - M) + so * __expf(mo - M);
        m = M;
    }
    sm[tid] = m; ss[tid] = s;
    __syncthreads();
    for (int st = 128; st > 0; st >>= 1) {
        if (tid < st) {
            float m1 = sm[tid], m2 = sm[tid + st];
            float s1 = ss[tid], s2 = ss[tid + st];
            float M = fmaxf(m1, m2);
            sm[tid] = M;
            ss[tid] = s1 * __expf(m1 - M) + s2 * __expf(m2 - M);
        }
        __syncthreads();
    }
    if (tid == 0) {
        float lse_tot = sm[0] + logf(ss[0]);

        float mp = -3.0e38f, sp = 0.0f;
        #pragma unroll
        for (int p = 0; p < 4; p++) {
            float mo = g_posm[b * 4 + p], so = g_poss[b * 4 + p];
            float M = fmaxf(mp, mo);
            sp = sp * __expf(mp - M) + so * __expf(mo - M);
            mp = M;
        }
        // s_*labels keeps negatives as exp(0)=1: B*K - K = 261632 of them
        float Mp = fmaxf(mp, 0.0f);
        float Sp = sp * __expf(mp - Mp) + 261632.0f * __expf(-Mp);
        float lse_p = Mp + logf(Sp);

        g_loss[b] = -lse_p + logf(511.0f) + lse_tot;     // num_p = 512 -> 511
    }
}

__global__ void reduce2(float* __restrict__ out)
{
    __shared__ float sm[512];
    const int tid = threadIdx.x;
    sm[tid] = g_loss[tid];
    __syncthreads();
    for (int st = 256; st > 0; st >>= 1) {
        if (tid < st) sm[tid] += sm[tid + st];
        __syncthreads();
    }
    if (tid == 0) out[0] = sm[0] * (1.0f / 512.0f);
}

// ---------------------------------------------------------------------------
extern "C" void kernel_launch(void* const* d_in, const int* in_sizes, int n_in,
                              void* d_out, int out_size)
{
    const float* Q    = (const float*)d_in[0];   // [512,128]
    const float* Km   = (const float*)d_in[1];   // [512,512,128]
    const int*   sidx = (const int*)  d_in[2];   // [512]

    cudaFuncSetAttribute(gemm_lse_hmma, cudaFuncAttributeMaxDynamicSharedMemorySize, SMEM_SZ);

    qconv<<<16, 256>>>(Q);
    gemm_lse_hmma<<<NTILES, 256, SMEM_SZ>>>(Km, sidx);
    reduce1<<<BQ, 256>>>();
    reduce2<<<1, 512>>>((float*)d_out);
}